// round 17
// baseline (speedup 1.0000x reference)
#include <cuda_runtime.h>
#include <cstdint>

#define T_STEPS 2048
#define BATCH   64
#define IN_DIM  128
#define HDIM    256
#define OUT_DIM 128
#define NTHR    512
#define NBLK    128           // 16 groups (4 batch rows) x 8 ranks (32 h-cols)
#define WOPAD   272

// smem layout (floats)
#define OFF_ACT   0                       // [2][384][4]  = 3072
#define OFF_WOUT  3072                    // [16][272]    = 4352
#define OFF_P     7424                    // [8][128][4]  = 4096
#define OFF_G     11520                   // [128][4]     = 512
#define OFF_BIAS  12032                   // 128
#define OFF_BOUT  12160                   // 16
#define OFF_PX    12176                   // [2][1024] float4 slots = 8192 floats
#define SMEM_FLOATS 20368
#define SMEM_BYTES (SMEM_FLOATS * 4)      // 81472

// persistent exchange state: tagged h pairs {h, step-tag}, double-buffered.
// Tags strictly monotonic across launches (epoch) -> no reset, replay-safe.
__device__ float2   g_hT[16][2][HDIM * 4];   // [grp][buf][col*4 + r] = {h, tag}
__device__ unsigned g_epoch[16];

__device__ __forceinline__ float sigm(float x) {
    return __fdividef(1.0f, 1.0f + __expf(-x));
}
__device__ __forceinline__ float tanh_fast(float x) {
    return __fdividef(2.0f, 1.0f + __expf(-2.0f * x)) - 1.0f;
}

__global__ void __launch_bounds__(NTHR, 1) lstm_pipe_kernel(
    const float* __restrict__ input,   // [T, B, IN]
    const float* __restrict__ W_ih,    // [4H, IN]
    const float* __restrict__ W_hh,    // [4H, H]
    const float* __restrict__ b_ih,    // [4H]
    const float* __restrict__ b_hh,    // [4H]
    const float* __restrict__ W_out,   // [OUT, H]
    const float* __restrict__ b_out,   // [OUT]
    float* __restrict__ out,
    int out_size)
{
    extern __shared__ float sm[];
    float* sAct  = sm + OFF_ACT;   // [buf][k][r]: k<128 x, k>=128 h
    float* sWo   = sm + OFF_WOUT;
    float* sP    = sm + OFF_P;     // split-K partials [8][128][4]
    float* sG    = sm + OFF_G;     // reduced gates [m][r]
    float* sBias = sm + OFF_BIAS;
    float* sBOut = sm + OFF_BOUT;
    // sPx: thread-private x-gate partial staging, [slot][2*512] ulonglong2
    ulonglong2* sPx = (ulonglong2*)(sm + OFF_PX);

    const int tid  = threadIdx.x;
    const int bid  = blockIdx.x;
    const int grp  = bid >> 3;
    const int rank = bid & 7;
    const int rbase = grp * 4;
    const int cb    = rank * 32;

    const unsigned e = *((volatile unsigned*)&g_epoch[grp]);   // uniform in group

    // ---- GEMM mapping (R13): col-pair m2 = tid&63 -> cols {2m2, 2m2+1};
    //      kq = tid>>6 (0..7) is warp-uniform -> activation LDS broadcasts ----
    const int m2 = tid & 63;
    const int kq = tid >> 6;
    const int c0 = 2 * m2, c1 = c0 + 1;
    const int grow0 = (c0 >> 5) * HDIM + cb + (c0 & 31);
    const int grow1 = grow0 + 1;

    // ---- weights in registers: 2 cols x (16 x-k + 32 h-k) = 96 regs ----
    float wx0[16], wx1[16], wh0[32], wh1[32];
    {
        const float* s0 = W_ih + (size_t)grow0 * IN_DIM + kq * 16;
        const float* s1 = W_ih + (size_t)grow1 * IN_DIM + kq * 16;
        #pragma unroll
        for (int i = 0; i < 16; i++) { wx0[i] = __ldg(s0 + i); wx1[i] = __ldg(s1 + i); }
        const float* h0 = W_hh + (size_t)grow0 * HDIM + kq * 32;
        const float* h1 = W_hh + (size_t)grow1 * HDIM + kq * 32;
        #pragma unroll
        for (int i = 0; i < 32; i++) { wh0[i] = __ldg(h0 + i); wh1[i] = __ldg(h1 + i); }
    }

    // ---- smem preload ----
    for (int i = tid; i < 16 * HDIM; i += NTHR) {
        int o = i >> 8, k = i & 255;
        sWo[o * WOPAD + k] = W_out[(rank * 16 + o) * HDIM + k];
    }
    if (tid < 128) {
        int gr = (tid >> 5) * HDIM + cb + (tid & 31);
        sBias[tid] = b_ih[gr] + b_hh[gr];
    }
    if (tid < 16) sBOut[tid] = b_out[rank * 16 + tid];

    // zero both act buffers (h_0 = 0); x_0 -> A[0], x_1 -> A[1] (transposed)
    for (int i = tid; i < 2 * 384 * 4; i += NTHR) sAct[i] = 0.0f;
    __syncthreads();
    if (tid < 256) {
        int s  = tid >> 7;                 // which timestep (0 or 1)
        int r  = (tid >> 5) & 3, k5 = tid & 31;
        float4 v = *(const float4*)(input + ((size_t)s * BATCH + rbase + r) * IN_DIM + k5 * 4);
        float* dst = sAct + s * 1536;
        dst[(k5 * 4 + 0) * 4 + r] = v.x;
        dst[(k5 * 4 + 1) * 4 + r] = v.y;
        dst[(k5 * 4 + 2) * 4 + r] = v.z;
        dst[(k5 * 4 + 3) * 4 + r] = v.w;
    }
    __syncthreads();

    // ---- prologue: x-gate partials for t=0 -> sPx slot 0 ----
    {
        unsigned long long a001 = 0ULL, a023 = 0ULL, a101 = 0ULL, a123 = 0ULL;
        const ulonglong2* av = ((const ulonglong2*)sAct) + kq * 16;
        #pragma unroll
        for (int i = 0; i < 16; i++) {
            ulonglong2 p = av[i];
            unsigned long long wp0, wp1;
            unsigned u0 = __float_as_uint(wx0[i]), u1 = __float_as_uint(wx1[i]);
            asm("mov.b64 %0, {%1, %1};" : "=l"(wp0) : "r"(u0));
            asm("mov.b64 %0, {%1, %1};" : "=l"(wp1) : "r"(u1));
            asm("fma.rn.f32x2 %0, %1, %2, %0;" : "+l"(a001) : "l"(wp0), "l"(p.x));
            asm("fma.rn.f32x2 %0, %1, %2, %0;" : "+l"(a023) : "l"(wp0), "l"(p.y));
            asm("fma.rn.f32x2 %0, %1, %2, %0;" : "+l"(a101) : "l"(wp1), "l"(p.x));
            asm("fma.rn.f32x2 %0, %1, %2, %0;" : "+l"(a123) : "l"(wp1), "l"(p.y));
        }
        ulonglong2 q0; q0.x = a001; q0.y = a023;
        ulonglong2 q1; q1.x = a101; q1.y = a123;
        sPx[tid] = q0;          // slot 0, first half
        sPx[512 + tid] = q1;    // slot 0, second half
    }
    // no sync needed: sPx slots are thread-private

    const size_t Y_TOTAL = (size_t)T_STEPS * BATCH * OUT_DIM;
    const bool write_tail = (out_size >= (int)(Y_TOTAL + 2 * BATCH * HDIM));

    float c_reg = 0.0f;   // cell state (r=tid>>5, c=tid&31), threads 0-127

    for (int t = 0; t < T_STEPS; t++) {
        const int buf = t & 1;
        float* A  = sAct + buf * 1536;
        float* An = sAct + (1 - buf) * 1536;

        // ---- phase 1: speculative tagged-pair load (detect fused in data) ----
        const float4* hsrc = ((const float4*)g_hT[grp][buf]) + tid;
        float4 v;
        if (t > 0) v = __ldcg(hsrc);

        // ---- phase 2a: x-gate GEMM for step t+1 (covers the h_t tag latency) ----
        if (t + 1 < T_STEPS) {
            unsigned long long b001 = 0ULL, b023 = 0ULL, b101 = 0ULL, b123 = 0ULL;
            const ulonglong2* av = ((const ulonglong2*)An) + kq * 16;   // x_{t+1}
            #pragma unroll
            for (int i = 0; i < 16; i++) {
                ulonglong2 p = av[i];
                unsigned long long wp0, wp1;
                unsigned u0 = __float_as_uint(wx0[i]), u1 = __float_as_uint(wx1[i]);
                asm("mov.b64 %0, {%1, %1};" : "=l"(wp0) : "r"(u0));
                asm("mov.b64 %0, {%1, %1};" : "=l"(wp1) : "r"(u1));
                asm("fma.rn.f32x2 %0, %1, %2, %0;" : "+l"(b001) : "l"(wp0), "l"(p.x));
                asm("fma.rn.f32x2 %0, %1, %2, %0;" : "+l"(b023) : "l"(wp0), "l"(p.y));
                asm("fma.rn.f32x2 %0, %1, %2, %0;" : "+l"(b101) : "l"(wp1), "l"(p.x));
                asm("fma.rn.f32x2 %0, %1, %2, %0;" : "+l"(b123) : "l"(wp1), "l"(p.y));
            }
            ulonglong2 q0; q0.x = b001; q0.y = b023;
            ulonglong2 q1; q1.x = b101; q1.y = b123;
            const int ws = ((t + 1) & 1) * 1024;
            sPx[ws + tid] = q0;
            sPx[ws + 512 + tid] = q1;
        }

        // ---- phase 2b: reload this step's x partials (thread-private) ----
        unsigned long long a001, a023, a101, a123;
        {
            const int rs = buf * 1024;
            ulonglong2 q0 = sPx[rs + tid];
            ulonglong2 q1 = sPx[rs + 512 + tid];
            a001 = q0.x; a023 = q0.y; a101 = q1.x; a123 = q1.y;
        }

        // ---- phase 3: tag-check (retry until fresh) and land the fill ----
        if (t > 0) {
            const unsigned want = e + (unsigned)t;   // tag of h_t
            while (__float_as_uint(v.y) != want || __float_as_uint(v.w) != want)
                v = __ldcg(hsrc);
            ((float2*)A)[256 + tid] = make_float2(v.x, v.z);
        }
        __syncthreads();

        // ---- phase 4: h-part GEMM (K=256, 8-way split, 2 cols; critical) ----
        {
            const ulonglong2* av = ((const ulonglong2*)A) + 128 + kq * 32;
            #pragma unroll
            for (int i = 0; i < 32; i++) {
                ulonglong2 p = av[i];
                unsigned long long wp0, wp1;
                unsigned u0 = __float_as_uint(wh0[i]), u1 = __float_as_uint(wh1[i]);
                asm("mov.b64 %0, {%1, %1};" : "=l"(wp0) : "r"(u0));
                asm("mov.b64 %0, {%1, %1};" : "=l"(wp1) : "r"(u1));
                asm("fma.rn.f32x2 %0, %1, %2, %0;" : "+l"(a001) : "l"(wp0), "l"(p.x));
                asm("fma.rn.f32x2 %0, %1, %2, %0;" : "+l"(a023) : "l"(wp0), "l"(p.y));
                asm("fma.rn.f32x2 %0, %1, %2, %0;" : "+l"(a101) : "l"(wp1), "l"(p.x));
                asm("fma.rn.f32x2 %0, %1, %2, %0;" : "+l"(a123) : "l"(wp1), "l"(p.y));
            }
            unsigned u0, u1, u2, u3;
            asm("mov.b64 {%0, %1}, %2;" : "=r"(u0), "=r"(u1) : "l"(a001));
            asm("mov.b64 {%0, %1}, %2;" : "=r"(u2), "=r"(u3) : "l"(a023));
            *(float4*)(sP + (kq * 128 + c0) * 4) =
                make_float4(__uint_as_float(u0), __uint_as_float(u1),
                            __uint_as_float(u2), __uint_as_float(u3));
            asm("mov.b64 {%0, %1}, %2;" : "=r"(u0), "=r"(u1) : "l"(a101));
            asm("mov.b64 {%0, %1}, %2;" : "=r"(u2), "=r"(u3) : "l"(a123));
            *(float4*)(sP + (kq * 128 + c1) * 4) =
                make_float4(__uint_as_float(u0), __uint_as_float(u1),
                            __uint_as_float(u2), __uint_as_float(u3));
        }
        __syncthreads();

        // ---- phase 5: reduce+cell+tagged store (w0-3) | x-pref (w4-7) | y (w8-15) ----
        if (tid < 128) {
            const float4* p4 = (const float4*)sP;
            float b = sBias[tid];
            float4 s = make_float4(b, b, b, b);
            #pragma unroll
            for (int q = 0; q < 8; q++) {
                float4 pv = p4[q * 128 + tid];
                s.x += pv.x; s.y += pv.y; s.z += pv.z; s.w += pv.w;
            }
            *(float4*)(sG + tid * 4) = s;
            asm volatile("bar.sync 1, 128;" ::: "memory");

            const int r = tid >> 5, c = tid & 31;
            float gi = sG[(0 * 32 + c) * 4 + r];
            float gf = sG[(1 * 32 + c) * 4 + r];
            float gg = sG[(2 * 32 + c) * 4 + r];
            float go = sG[(3 * 32 + c) * 4 + r];
            float i_ = sigm(gi);
            float f_ = sigm(gf);
            float gv = tanh_fast(gg);
            float o_ = sigm(go);
            float cn = f_ * c_reg + i_ * gv;
            float hn = o_ * tanh_fast(cn);
            c_reg = cn;

            // one stcg.64 carries value AND completion tag (per-element sync)
            float2 pr;
            pr.x = hn;
            pr.y = __uint_as_float(e + (unsigned)t + 1u);
            __stcg(&g_hT[grp][1 - buf][(cb + c) * 4 + r], pr);

            if (t == T_STEPS - 1 && write_tail) {
                out[Y_TOTAL + (size_t)(rbase + r) * HDIM + cb + c] = hn;
                out[Y_TOTAL + BATCH * HDIM + (size_t)(rbase + r) * HDIM + cb + c] = cn;
            }
        } else if (tid < 256) {
            // x_{t+2} prefetch (transposed) into A[buf] x-region
            // (x_t there was consumed at step t-1 phase 2a)
            if (t + 2 < T_STEPS) {
                int xr = (tid - 128) >> 5, xk5 = (tid - 128) & 31;
                float4 xv = __ldcg((const float4*)(input
                        + ((size_t)(t + 2) * BATCH + rbase + xr) * IN_DIM + xk5 * 4));
                A[(xk5 * 4 + 0) * 4 + xr] = xv.x;
                A[(xk5 * 4 + 1) * 4 + xr] = xv.y;
                A[(xk5 * 4 + 2) * 4 + xr] = xv.z;
                A[(xk5 * 4 + 3) * 4 + xr] = xv.w;
            }
        } else if (t > 0) {
            const int slot = tid - 256;
            const int o = slot >> 4, ks = slot & 15;
            float y0 = 0.f, y1 = 0.f, y2 = 0.f, y3 = 0.f;
            const float* wo = sWo + o * WOPAD + ks;
            const float4* ah = ((const float4*)A) + 128 + ks;
            #pragma unroll
            for (int i = 0; i < 16; i++) {
                float w = wo[i * 16];
                float4 h4 = ah[i * 16];
                y0 += w * h4.x; y1 += w * h4.y; y2 += w * h4.z; y3 += w * h4.w;
            }
            #pragma unroll
            for (int s = 1; s <= 8; s <<= 1) {
                y0 += __shfl_xor_sync(0xffffffffu, y0, s);
                y1 += __shfl_xor_sync(0xffffffffu, y1, s);
                y2 += __shfl_xor_sync(0xffffffffu, y2, s);
                y3 += __shfl_xor_sync(0xffffffffu, y3, s);
            }
            if (ks == 0) {
                float b = sBOut[o];
                size_t yb = ((size_t)(t - 1) * BATCH + rbase) * OUT_DIM
                            + (size_t)rank * 16 + o;
                out[yb + 0 * OUT_DIM] = y0 + b;
                out[yb + 1 * OUT_DIM] = y1 + b;
                out[yb + 2 * OUT_DIM] = y2 + b;
                out[yb + 3 * OUT_DIM] = y3 + b;
            }
        }
        __syncthreads();
    }

    // ---- tail: y_{T-1} from h_T (buf 0, tag e+T_STEPS) ----
    {
        float* A = sAct;   // buf 0
        const float4* hsrc = ((const float4*)g_hT[grp][0]) + tid;
        const unsigned want = e + (unsigned)T_STEPS;
        float4 v = __ldcg(hsrc);
        while (__float_as_uint(v.y) != want || __float_as_uint(v.w) != want)
            v = __ldcg(hsrc);
        ((float2*)A)[256 + tid] = make_float2(v.x, v.z);
        __syncthreads();
        if (tid >= 256) {
            const int slot = tid - 256;
            const int o = slot >> 4, ks = slot & 15;
            float y0 = 0.f, y1 = 0.f, y2 = 0.f, y3 = 0.f;
            const float* wo = sWo + o * WOPAD + ks;
            const float4* ah = ((const float4*)A) + 128 + ks;
            #pragma unroll
            for (int i = 0; i < 16; i++) {
                float w = wo[i * 16];
                float4 h4 = ah[i * 16];
                y0 += w * h4.x; y1 += w * h4.y; y2 += w * h4.z; y3 += w * h4.w;
            }
            #pragma unroll
            for (int s = 1; s <= 8; s <<= 1) {
                y0 += __shfl_xor_sync(0xffffffffu, y0, s);
                y1 += __shfl_xor_sync(0xffffffffu, y1, s);
                y2 += __shfl_xor_sync(0xffffffffu, y2, s);
                y3 += __shfl_xor_sync(0xffffffffu, y3, s);
            }
            if (ks == 0) {
                float b = sBOut[o];
                size_t yb = ((size_t)(T_STEPS - 1) * BATCH + rbase) * OUT_DIM
                            + (size_t)rank * 16 + o;
                out[yb + 0 * OUT_DIM] = y0 + b;
                out[yb + 1 * OUT_DIM] = y1 + b;
                out[yb + 2 * OUT_DIM] = y2 + b;
                out[yb + 3 * OUT_DIM] = y3 + b;
            }
        }
        __syncthreads();
        // advance epoch for the next launch/replay (tags stay monotonic)
        if (rank == 0 && tid == 0)
            *((volatile unsigned*)&g_epoch[grp]) = e + (unsigned)T_STEPS;
    }
}

extern "C" void kernel_launch(void* const* d_in, const int* in_sizes, int n_in,
                              void* d_out, int out_size) {
    const float* input = (const float*)d_in[0];
    const float* W_ih  = (const float*)d_in[1];
    const float* W_hh  = (const float*)d_in[2];
    const float* b_ih  = (const float*)d_in[3];
    const float* b_hh  = (const float*)d_in[4];
    const float* W_out = (const float*)d_in[5];
    const float* b_out = (const float*)d_in[6];
    float* out = (float*)d_out;
    (void)in_sizes; (void)n_in;

    cudaFuncSetAttribute(lstm_pipe_kernel,
                         cudaFuncAttributeMaxDynamicSharedMemorySize, SMEM_BYTES);
    lstm_pipe_kernel<<<NBLK, NTHR, SMEM_BYTES>>>(
        input, W_ih, W_hh, b_ih, b_hh, W_out, b_out, out, out_size);
}